// round 7
// baseline (speedup 1.0000x reference)
#include <cuda_runtime.h>
#include <cuda_bf16.h>

// CTC forward: one block (128 threads = 4 warps) per batch element.
// Thread i owns pair (E_i = state 2i, O_i = state 2i+1) in registers.
// Only O crosses threads. Per step:
//   bar.sync(buf) -> LDS O_{i-1} -> 3-way lse -> STS nO -> bar.arrive(other buf)
//   -> all off-chain work (nE, E2, emission prefetch) AFTER the arrive.
// Named barriers 1,2 (cnt=256: 128 arrive + 128 sync per instance).
// Alphas in log2 domain; lse via raw MUFU ex2/lg2.

#define NEGF  (-1e30f)
#define LOG2E 1.4426950408889634f
#define LN2   0.6931471805599453f
#define MAXB  1024

#define BAR_SYNC(id)   asm volatile("bar.sync %0, 256;"   :: "r"(id) : "memory")
#define BAR_ARRIVE(id) asm volatile("bar.arrive %0, 256;" :: "r"(id) : "memory")

__device__ float        g_per_ex[MAXB];
__device__ unsigned int g_count = 0;

__device__ __forceinline__ float ex2(float x) { float r; asm("ex2.approx.f32 %0, %1;" : "=f"(r) : "f"(x)); return r; }
__device__ __forceinline__ float lg2(float x) { float r; asm("lg2.approx.f32 %0, %1;" : "=f"(r) : "f"(x)); return r; }

__device__ __forceinline__ float lse2(float a, float b) {
    float m = fmaxf(a, b);
    float d = fminf(a, b) - m;          // <= 0
    return m + lg2(1.0f + ex2(d));
}

__global__ __launch_bounds__(128, 1)
void ctc_forward_kernel(const float* __restrict__ pred,           // (B, T, C)
                        const int*   __restrict__ targets,        // (B, L)
                        const int*   __restrict__ pred_lengths,   // (B,)
                        const int*   __restrict__ target_lengths, // (B,)
                        float*       __restrict__ out,
                        int T, int C, int L, int B)
{
    __shared__ float sO[2][130];   // O_i at [i+1]; [0] = NEG sentinel
    __shared__ float sOf[128];
    __shared__ float sEf[129];
    __shared__ unsigned int s_last;
    __shared__ float sred[4];

    const int b    = blockIdx.x;
    const int i    = threadIdx.x;        // pair index 0..127
    const int w    = i >> 5;
    const int lane = i & 31;

    const int  li   = (i < L) ? i : (L - 1);
    const int  lbl  = targets[(size_t)b * L + li];
    const int  prev = (li >= 1) ? targets[(size_t)b * L + li - 1] : -1;
    const bool skip = (lbl != 0) && (lbl != prev);

    const float* rowp = pred + (size_t)b * T * C;

    int pl = pred_lengths[b];
    int Teff = pl < T ? pl : T; if (Teff < 1) Teff = 1;
    const int steps = Teff - 1;          // updates at t = 1..steps

    // ---- init (t = 0) ----
    float eb0 = __ldg(rowp) * LOG2E;
    float el0 = __ldg(rowp + lbl) * LOG2E;
    float E  = (i == 0) ? eb0 : NEGF;    // state 2i
    float O  = (i == 0) ? el0 : NEGF;    // state 2i+1
    float E2 = NEGF;                     // state 2L (thread 127, used iff L==128)

    if (i == 0) { sO[0][0] = NEGF; sO[1][0] = NEGF; }
    sO[1][i + 1] = O;                    // t=1 reads buf 1

    float m1 = fmaxf(O, E);              // precomputed own-max

    // emission prefetch ring, depth 8
    float eb[8], el[8];
#pragma unroll
    for (int j = 0; j < 8; j++) {
        int tt = 1 + j; if (tt > steps) tt = steps; if (tt < 0) tt = 0;
        const float* p = rowp + (size_t)tt * C;
        eb[j] = __ldg(p) * LOG2E;
        el[j] = __ldg(p + lbl) * LOG2E;
    }

    BAR_ARRIVE(2);                       // publish initial buf-1 contents

    int t = 1;
    // ---- main loop: unroll 8; step j has parity p = (j&1)^1 (t0 odd) ----
    for (; t + 7 <= steps; t += 8) {
#pragma unroll
        for (int j = 0; j < 8; j++) {
            const int p = (j & 1) ^ 1;          // read buf p, write buf p^1
            BAR_SYNC(1 + p);
            // --- critical chain ---
            float Om1  = sO[p][i];
            float Om1s = skip ? Om1 : NEGF;
            float mO   = fmaxf(m1, Om1s);
            float s3   = ex2(O - mO) + ex2(E - mO) + ex2(Om1s - mO);
            float nO   = mO + lg2(s3) + el[j];
            sO[p ^ 1][i + 1] = nO;
            BAR_ARRIVE(1 + (p ^ 1));
            // --- off-chain (overlaps other warps' waits) ---
            float nE = lse2(E, Om1) + eb[j];
            if (i == 127) E2 = lse2(E2, O) + eb[j];   // old O
            O = nO; E = nE;
            m1 = fmaxf(O, E);
            int tn = t + j + 8; if (tn > steps) tn = steps;
            const float* pp = rowp + (size_t)tn * C;
            eb[j] = __ldg(pp) * LOG2E;
            el[j] = __ldg(pp + lbl) * LOG2E;
        }
    }
    // ---- tail (< 8 steps), runtime parity ----
    for (; t <= steps; t++) {
        const int p = t & 1;
        BAR_SYNC(1 + p);
        float Om1  = sO[p][i];
        float Om1s = skip ? Om1 : NEGF;
        const float* pp = rowp + (size_t)t * C;
        float ebx = __ldg(pp) * LOG2E;
        float elx = __ldg(pp + lbl) * LOG2E;
        float mO  = fmaxf(m1, Om1s);
        float s3  = ex2(O - mO) + ex2(E - mO) + ex2(Om1s - mO);
        float nO  = mO + lg2(s3) + elx;
        sO[p ^ 1][i + 1] = nO;
        BAR_ARRIVE(1 + (p ^ 1));
        float nE = lse2(E, Om1) + ebx;
        if (i == 127) E2 = lse2(E2, O) + ebx;
        O = nO; E = nE;
        m1 = fmaxf(O, E);
    }

    // ---- gather + per-example loss ----
    sOf[i] = O;
    sEf[i] = E;
    if (i == 127) sEf[128] = E2;
    __syncthreads();

    if (i == 0) {
        int tl = target_lengths[b];
        int tlc = tl; if (tlc < 1) tlc = 1; if (tlc > L) tlc = L;
        float l1 = sOf[tlc - 1];        // state 2*tl - 1
        float l2 = sEf[tlc];            // state 2*tl
        float per = -(lse2(l1, l2) * LN2);
        if (per > 1e29f) per = 0.0f;
        int denom = tl < 1 ? 1 : tl;
        g_per_ex[b] = per / (float)denom;
        __threadfence();
        unsigned prevc = atomicAdd(&g_count, 1u);
        s_last = (prevc == (unsigned)(B - 1)) ? 1u : 0u;
    }
    __syncthreads();

    // ---- last block computes the batch mean (deterministic fixed order) ----
    if (s_last) {
        float v = 0.f;
        for (int idx = i; idx < B; idx += 128)
            v += *((volatile float*)&g_per_ex[idx]);
#pragma unroll
        for (int o = 16; o > 0; o >>= 1)
            v += __shfl_down_sync(0xffffffffu, v, o);
        if (lane == 0) sred[w] = v;
        __syncthreads();
        if (i == 0) {
            float tot = sred[0] + sred[1] + sred[2] + sred[3];
            out[0] = tot / (float)B;
            g_count = 0;    // reset for next graph replay
        }
    }
}

extern "C" void kernel_launch(void* const* d_in, const int* in_sizes, int n_in,
                              void* d_out, int out_size)
{
    const float* pred           = (const float*)d_in[0];
    const int*   targets        = (const int*)d_in[1];
    const int*   pred_lengths   = (const int*)d_in[2];
    const int*   target_lengths = (const int*)d_in[3];

    const int B = in_sizes[2];
    const int L = in_sizes[1] / B;
    const int C = 128;
    const int T = (in_sizes[0] / B) / C;

    ctc_forward_kernel<<<B, 128>>>(pred, targets, pred_lengths, target_lengths,
                                   (float*)d_out, T, C, L, B);
}